// round 1
// baseline (speedup 1.0000x reference)
#include <cuda_runtime.h>
#include <cuda_bf16.h>

#define LDIM 2048
#define NTH  1024
#define BMAX 4096

__device__ float g_row_loss[BMAX];

// Monotone map: ascending uint <-> ascending float (total order, -0 < +0).
__device__ __forceinline__ unsigned f2u_asc(float f) {
    unsigned u = __float_as_uint(f);
    return (u & 0x80000000u) ? ~u : (u | 0x80000000u);
}

__global__ __launch_bounds__(NTH, 2)
void listmle_row_kernel(const float* __restrict__ preds,
                        const float* __restrict__ tgts) {
    __shared__ unsigned long long keys[LDIM];
    __shared__ float sp[LDIM];
    __shared__ float red[33];

    const int row  = blockIdx.x;
    const int tid  = threadIdx.x;
    const int lane = tid & 31;
    const int wid  = tid >> 5;

    const float* p = preds + (size_t)row * LDIM;
    const float* t = tgts  + (size_t)row * LDIM;

    // Load predictions to smem; build 64-bit keys: descending target, stable by index.
    #pragma unroll
    for (int i = tid; i < LDIM; i += NTH) {
        sp[i] = p[i];
        unsigned s = f2u_asc(t[i]);
        keys[i] = ((unsigned long long)(~s) << 32) | (unsigned)i;
    }
    __syncthreads();

    // Bitonic sort ascending on 64-bit keys (2048 elems, 1024 threads, 2/thread).
    for (int k = 2; k <= LDIM; k <<= 1) {
        for (int j = k >> 1; j > 0; j >>= 1) {
            #pragma unroll
            for (int base = tid; base < LDIM; base += NTH) {
                int ixj = base ^ j;
                if (ixj > base) {
                    unsigned long long a = keys[base];
                    unsigned long long b = keys[ixj];
                    bool up = ((base & k) == 0);
                    if ((a > b) == up) { keys[base] = b; keys[ixj] = a; }
                }
            }
            __syncthreads();
        }
    }

    // Row max of predictions (for exp stabilization).
    float lm = -3.402823466e+38f;
    #pragma unroll
    for (int i = tid; i < LDIM; i += NTH) lm = fmaxf(lm, sp[i]);
    #pragma unroll
    for (int off = 16; off; off >>= 1) lm = fmaxf(lm, __shfl_xor_sync(0xFFFFFFFFu, lm, off));
    if (lane == 0) red[wid] = lm;
    __syncthreads();
    if (wid == 0) {
        float v = red[lane];
        #pragma unroll
        for (int off = 16; off; off >>= 1) v = fmaxf(v, __shfl_xor_sync(0xFFFFFFFFu, v, off));
        if (lane == 0) red[32] = v;
    }
    __syncthreads();
    const float m = red[32];
    __syncthreads();   // red[] gets reused below

    // Reverse-order suffix sums: thread owns reversed positions 2*tid, 2*tid+1.
    // sorted position i -> reversed q = LDIM-1-i.
    const int i0 = LDIM - 1 - 2 * tid;   // reversed q0 = 2*tid
    const int i1 = i0 - 1;               // reversed q1 = 2*tid+1
    const unsigned idx0 = (unsigned)keys[i0];
    const unsigned idx1 = (unsigned)keys[i1];
    const float v0 = __expf(sp[idx0] - m);
    const float v1 = __expf(sp[idx1] - m);
    const float ts = v0 + v1;

    // Inclusive scan of per-thread sums across the block.
    float x = ts;
    #pragma unroll
    for (int off = 1; off < 32; off <<= 1) {
        float y = __shfl_up_sync(0xFFFFFFFFu, x, off);
        if (lane >= off) x += y;
    }
    if (lane == 31) red[wid] = x;
    __syncthreads();
    if (wid == 0) {
        float w = red[lane];
        #pragma unroll
        for (int off = 1; off < 32; off <<= 1) {
            float y = __shfl_up_sync(0xFFFFFFFFu, w, off);
            if (lane >= off) w += y;
        }
        red[lane] = w;
    }
    __syncthreads();
    const float excl = (wid > 0 ? red[wid - 1] : 0.0f) + (x - ts);

    // Suffix sums S for the two sorted positions this thread owns.
    const float S0 = excl + v0;        // suffix sum at sorted pos i0
    const float S1 = excl + v0 + v1;   // suffix sum at sorted pos i1
    const float eps = 1e-10f;
    const float P0 = v0 / (S0 + eps);
    const float P1 = v1 / (S1 + eps);
    float term = -(__logf(P0 + eps) + __logf(P1 + eps));

    // Block reduce of loss terms (fixed order -> deterministic).
    #pragma unroll
    for (int off = 16; off; off >>= 1) term += __shfl_xor_sync(0xFFFFFFFFu, term, off);
    __syncthreads();
    if (lane == 0) red[wid] = term;
    __syncthreads();
    if (tid == 0) {
        float tot = 0.0f;
        #pragma unroll
        for (int w = 0; w < 32; w++) tot += red[w];
        g_row_loss[row] = tot;
    }
}

__global__ void listmle_mean_kernel(float* __restrict__ out, int B) {
    __shared__ float s[NTH];
    float acc = 0.0f;
    for (int i = threadIdx.x; i < B; i += NTH) acc += g_row_loss[i];
    s[threadIdx.x] = acc;
    __syncthreads();
    #pragma unroll
    for (int stride = NTH / 2; stride > 0; stride >>= 1) {
        if (threadIdx.x < stride) s[threadIdx.x] += s[threadIdx.x + stride];
        __syncthreads();
    }
    if (threadIdx.x == 0) out[0] = s[0] / (float)B;
}

extern "C" void kernel_launch(void* const* d_in, const int* in_sizes, int n_in,
                              void* d_out, int out_size) {
    const float* preds = (const float*)d_in[0];
    const float* tgts  = (const float*)d_in[1];
    int B = in_sizes[0] / LDIM;
    if (B > BMAX) B = BMAX;
    listmle_row_kernel<<<B, NTH>>>(preds, tgts);
    listmle_mean_kernel<<<1, NTH>>>((float*)d_out, B);
}

// round 2
// speedup vs baseline: 1.8130x; 1.8130x over previous
#include <cuda_runtime.h>
#include <cuda_bf16.h>

#define LDIM 2048
#define NTH  1024
#define BMAX 4096

__device__ float g_row_loss[BMAX];

// Monotone map: ascending uint <-> ascending float (total order).
__device__ __forceinline__ unsigned f2u_asc(float f) {
    unsigned u = __float_as_uint(f);
    return (u & 0x80000000u) ? ~u : (u | 0x80000000u);
}

__device__ __forceinline__ void cmpswap(unsigned long long& a, unsigned long long& b, bool up) {
    if ((a > b) == up) { unsigned long long t = a; a = b; b = t; }
}

// One bitonic exchange pass at element-distance j = 2*mask, via warp shuffle.
// Both of this thread's elements (even/odd slots) have the same lower/up flags.
__device__ __forceinline__ void shfl_pass(unsigned long long& e0, unsigned long long& e1,
                                          int mask, bool up, bool lower) {
    unsigned long long o0 = __shfl_xor_sync(0xFFFFFFFFu, e0, mask);
    unsigned long long o1 = __shfl_xor_sync(0xFFFFFFFFu, e1, mask);
    bool keepmin = (lower == up);
    if (keepmin) {
        e0 = (e0 < o0) ? e0 : o0;
        e1 = (e1 < o1) ? e1 : o1;
    } else {
        e0 = (e0 > o0) ? e0 : o0;
        e1 = (e1 > o1) ? e1 : o1;
    }
}

__global__ __launch_bounds__(NTH, 2)
void listmle_row_kernel(const float* __restrict__ preds,
                        const float* __restrict__ tgts) {
    __shared__ unsigned long long keys[LDIM];
    __shared__ float red[33];

    const int row  = blockIdx.x;
    const int tid  = threadIdx.x;
    const int lane = tid & 31;
    const int wid  = tid >> 5;

    // Vectorized load: thread owns elements 2*tid, 2*tid+1.
    const float2 pv = ((const float2*)(preds + (size_t)row * LDIM))[tid];
    const float2 tv = ((const float2*)(tgts  + (size_t)row * LDIM))[tid];

    // key: high 32 = descending-target order, low 32 = raw pred bits (payload).
    unsigned long long e0 = ((unsigned long long)(~f2u_asc(tv.x)) << 32) | __float_as_uint(pv.x);
    unsigned long long e1 = ((unsigned long long)(~f2u_asc(tv.y)) << 32) | __float_as_uint(pv.y);

    // Block max of predictions (for exp stabilization) while data is in regs.
    float lm = fmaxf(pv.x, pv.y);
    #pragma unroll
    for (int off = 16; off; off >>= 1) lm = fmaxf(lm, __shfl_xor_sync(0xFFFFFFFFu, lm, off));
    if (lane == 0) red[wid] = lm;
    __syncthreads();
    if (wid == 0) {
        float v = red[lane];
        #pragma unroll
        for (int off = 16; off; off >>= 1) v = fmaxf(v, __shfl_xor_sync(0xFFFFFFFFu, v, off));
        if (lane == 0) red[32] = v;
    }
    __syncthreads();
    const float m = red[32];
    __syncthreads();  // red[] reused later

    // ---- Phase A: bitonic stages k=2..64 entirely in registers/shuffles ----
    cmpswap(e0, e1, (tid & 1) == 0);                      // stage k=2 (j=1)
    #pragma unroll
    for (int K = 2; K <= 6; K++) {                        // stages k=4..64
        bool up = ((tid & (1u << (K - 1))) == 0);
        #pragma unroll
        for (int msk = (1 << (K - 2)); msk >= 1; msk >>= 1)  // j=2^(K-1)..2
            shfl_pass(e0, e1, msk, up, (tid & msk) == 0);
        cmpswap(e0, e1, up);                              // j=1
    }

    // ---- Phase B: stages k=128..2048, j>=64 in smem, j<=32 in registers ----
    keys[2 * tid]     = e0;
    keys[2 * tid + 1] = e1;
    __syncthreads();
    #pragma unroll
    for (int K = 7; K <= 11; K++) {
        const int k = 1 << K;
        #pragma unroll
        for (int j = k >> 1; j >= 64; j >>= 1) {
            int i = ((tid & ~(j - 1)) << 1) | (tid & (j - 1));
            bool up = ((i & k) == 0);
            unsigned long long a = keys[i];
            unsigned long long b = keys[i + j];
            if ((a > b) == up) { keys[i] = b; keys[i + j] = a; }
            __syncthreads();
        }
        e0 = keys[2 * tid];
        e1 = keys[2 * tid + 1];
        bool up = ((tid & (k >> 1)) == 0);
        #pragma unroll
        for (int msk = 16; msk >= 1; msk >>= 1)
            shfl_pass(e0, e1, msk, up, (tid & msk) == 0);
        cmpswap(e0, e1, up);
        if (K < 11) {
            keys[2 * tid]     = e0;
            keys[2 * tid + 1] = e1;
            __syncthreads();
        }
    }
    // Now e0/e1 are sorted positions 2*tid, 2*tid+1 (pos 0 = highest target).

    const float v0 = __expf(__uint_as_float((unsigned)e0) - m);
    const float v1 = __expf(__uint_as_float((unsigned)e1) - m);
    const float ts = v0 + v1;

    // Descending (suffix) inclusive scan of per-thread sums across the block.
    float x = ts;
    #pragma unroll
    for (int off = 1; off < 32; off <<= 1) {
        float y = __shfl_down_sync(0xFFFFFFFFu, x, off);
        if (lane < 32 - off) x += y;
    }
    if (lane == 0) red[wid] = x;   // warp totals
    __syncthreads();
    if (wid == 0) {
        float w = red[lane];
        #pragma unroll
        for (int off = 1; off < 32; off <<= 1) {
            float y = __shfl_down_sync(0xFFFFFFFFu, w, off);
            if (lane < 32 - off) w += y;
        }
        red[lane] = w;             // inclusive suffix over warp totals
    }
    __syncthreads();
    const float warp_after  = (wid < 31) ? red[wid + 1] : 0.0f;
    const float suffix_excl = warp_after + (x - ts);  // sum over all positions > 2*tid+1

    const float S1 = suffix_excl + v1;       // suffix sum at sorted pos 2*tid+1
    const float S0 = S1 + v0;                // suffix sum at sorted pos 2*tid
    const float eps = 1e-10f;
    const float P0 = v0 / (S0 + eps);
    const float P1 = v1 / (S1 + eps);
    float term = -(__logf(P0 + eps) + __logf(P1 + eps));

    // Deterministic block reduction of loss terms.
    #pragma unroll
    for (int off = 16; off; off >>= 1) term += __shfl_xor_sync(0xFFFFFFFFu, term, off);
    __syncthreads();
    if (lane == 0) red[wid] = term;
    __syncthreads();
    if (tid == 0) {
        float tot = 0.0f;
        #pragma unroll
        for (int w = 0; w < 32; w++) tot += red[w];
        g_row_loss[row] = tot;
    }
}

__global__ void listmle_mean_kernel(float* __restrict__ out, int B) {
    __shared__ float s[NTH];
    float acc = 0.0f;
    for (int i = threadIdx.x; i < B; i += NTH) acc += g_row_loss[i];
    s[threadIdx.x] = acc;
    __syncthreads();
    #pragma unroll
    for (int stride = NTH / 2; stride > 0; stride >>= 1) {
        if (threadIdx.x < stride) s[threadIdx.x] += s[threadIdx.x + stride];
        __syncthreads();
    }
    if (threadIdx.x == 0) out[0] = s[0] / (float)B;
}

extern "C" void kernel_launch(void* const* d_in, const int* in_sizes, int n_in,
                              void* d_out, int out_size) {
    const float* preds = (const float*)d_in[0];
    const float* tgts  = (const float*)d_in[1];
    int B = in_sizes[0] / LDIM;
    if (B > BMAX) B = BMAX;
    listmle_row_kernel<<<B, NTH>>>(preds, tgts);
    listmle_mean_kernel<<<1, NTH>>>((float*)d_out, B);
}

// round 3
// speedup vs baseline: 2.0307x; 1.1200x over previous
#include <cuda_runtime.h>
#include <cuda_bf16.h>

#define LDIM 2048
#define NTH  1024
#define BMAX 4096

__device__ float g_row_loss[BMAX];

// Monotone map: ascending uint <-> ascending float (total order).
__device__ __forceinline__ unsigned f2u_asc(float f) {
    unsigned u = __float_as_uint(f);
    return (u & 0x80000000u) ? ~u : (u | 0x80000000u);
}

__device__ __forceinline__ void cmpswap(unsigned& a, unsigned& b, bool up) {
    if ((a > b) == up) { unsigned t = a; a = b; b = t; }
}

// One bitonic exchange pass at element-distance j = 2*mask, via warp shuffle.
__device__ __forceinline__ void shfl_pass(unsigned& e0, unsigned& e1,
                                          int mask, bool up, bool lower) {
    unsigned o0 = __shfl_xor_sync(0xFFFFFFFFu, e0, mask);
    unsigned o1 = __shfl_xor_sync(0xFFFFFFFFu, e1, mask);
    if (lower == up) {
        e0 = umin(e0, o0);
        e1 = umin(e1, o1);
    } else {
        e0 = umax(e0, o0);
        e1 = umax(e1, o1);
    }
}

__global__ __launch_bounds__(NTH, 2)
void listmle_row_kernel(const float* __restrict__ preds,
                        const float* __restrict__ tgts) {
    __shared__ unsigned K[LDIM];
    __shared__ float vs[LDIM];
    __shared__ float red[33];

    const int row  = blockIdx.x;
    const int tid  = threadIdx.x;
    const int lane = tid & 31;
    const int wid  = tid >> 5;

    const float2 pv = ((const float2*)(preds + (size_t)row * LDIM))[tid];
    const float2 tv = ((const float2*)(tgts  + (size_t)row * LDIM))[tid];

    const unsigned k0 = f2u_asc(tv.x);
    const unsigned k1 = f2u_asc(tv.y);
    unsigned e0 = k0, e1 = k1;

    // Pre-zero scatter target (covered by the barrier in the max-reduce below).
    vs[2 * tid]     = 0.0f;
    vs[2 * tid + 1] = 0.0f;

    // Block max of predictions (exp stabilization).
    float lm = fmaxf(pv.x, pv.y);
    #pragma unroll
    for (int off = 16; off; off >>= 1) lm = fmaxf(lm, __shfl_xor_sync(0xFFFFFFFFu, lm, off));
    if (lane == 0) red[wid] = lm;
    __syncthreads();
    if (wid == 0) {
        float v = red[lane];
        #pragma unroll
        for (int off = 16; off; off >>= 1) v = fmaxf(v, __shfl_xor_sync(0xFFFFFFFFu, v, off));
        if (lane == 0) red[32] = v;
    }
    __syncthreads();
    const float m = red[32];
    __syncthreads();   // red[] reused later

    // ---- Phase A: bitonic stages k=2..64, registers/shuffles only ----
    cmpswap(e0, e1, (tid & 1) == 0);                      // stage k=2
    #pragma unroll
    for (int Ks = 2; Ks <= 6; Ks++) {                     // stages k=4..64
        bool up = ((tid & (1u << (Ks - 1))) == 0);
        #pragma unroll
        for (int msk = (1 << (Ks - 2)); msk >= 1; msk >>= 1)
            shfl_pass(e0, e1, msk, up, (tid & msk) == 0);
        cmpswap(e0, e1, up);
    }

    // ---- Phase B: stages k=128..2048, j>=64 in smem, j<=32 in regs ----
    K[2 * tid]     = e0;
    K[2 * tid + 1] = e1;
    __syncthreads();
    #pragma unroll
    for (int Ks = 7; Ks <= 11; Ks++) {
        const int k = 1 << Ks;
        #pragma unroll
        for (int j = k >> 1; j >= 64; j >>= 1) {
            int i = ((tid & ~(j - 1)) << 1) | (tid & (j - 1));
            bool up = ((i & k) == 0);
            unsigned a = K[i];
            unsigned b = K[i + j];
            if ((a > b) == up) { K[i] = b; K[i + j] = a; }
            __syncthreads();
        }
        e0 = K[2 * tid];
        e1 = K[2 * tid + 1];
        bool up = ((tid & (k >> 1)) == 0);
        #pragma unroll
        for (int msk = 16; msk >= 1; msk >>= 1)
            shfl_pass(e0, e1, msk, up, (tid & msk) == 0);
        cmpswap(e0, e1, up);
        K[2 * tid]     = e0;
        K[2 * tid + 1] = e1;
        __syncthreads();
    }
    // K[] now ascending by target.

    // Binary search own keys -> sorted positions; scatter v.
    const float v0 = __expf(pv.x - m);
    const float v1 = __expf(pv.y - m);
    int p0 = 0, p1 = 0;
    #pragma unroll
    for (int s = 1024; s >= 1; s >>= 1) {
        if (K[p0 + s - 1] < k0) p0 += s;
        if (K[p1 + s - 1] < k1) p1 += s;
    }
    vs[p0] = v0;
    vs[p1] = v1;
    __syncthreads();

    // Ascending inclusive prefix scan over vs; thread owns positions 2tid, 2tid+1.
    const float a0 = vs[2 * tid];
    const float a1 = vs[2 * tid + 1];
    const float ts = a0 + a1;
    float x = ts;
    #pragma unroll
    for (int off = 1; off < 32; off <<= 1) {
        float y = __shfl_up_sync(0xFFFFFFFFu, x, off);
        if (lane >= off) x += y;
    }
    if (lane == 31) red[wid] = x;
    __syncthreads();
    if (wid == 0) {
        float w = red[lane];
        #pragma unroll
        for (int off = 1; off < 32; off <<= 1) {
            float y = __shfl_up_sync(0xFFFFFFFFu, w, off);
            if (lane >= off) w += y;
        }
        red[lane] = w;
    }
    __syncthreads();
    const float excl = (wid > 0 ? red[wid - 1] : 0.0f) + (x - ts);

    // Inclusive prefix (ascending) == suffix sum in descending-target order.
    const float S0 = excl + a0;
    const float S1 = S0 + a1;
    const float eps = 1e-10f;
    const float P0 = a0 / (S0 + eps);
    const float P1 = a1 / (S1 + eps);
    float term = -(__logf(P0 + eps) + __logf(P1 + eps));

    // Deterministic block reduction.
    #pragma unroll
    for (int off = 16; off; off >>= 1) term += __shfl_xor_sync(0xFFFFFFFFu, term, off);
    __syncthreads();
    if (lane == 0) red[wid] = term;
    __syncthreads();
    if (tid == 0) {
        float tot = 0.0f;
        #pragma unroll
        for (int w = 0; w < 32; w++) tot += red[w];
        g_row_loss[row] = tot;
    }
}

__global__ void listmle_mean_kernel(float* __restrict__ out, int B) {
    __shared__ float s[NTH];
    float acc = 0.0f;
    for (int i = threadIdx.x; i < B; i += NTH) acc += g_row_loss[i];
    s[threadIdx.x] = acc;
    __syncthreads();
    #pragma unroll
    for (int stride = NTH / 2; stride > 0; stride >>= 1) {
        if (threadIdx.x < stride) s[threadIdx.x] += s[threadIdx.x + stride];
        __syncthreads();
    }
    if (threadIdx.x == 0) out[0] = s[0] / (float)B;
}

extern "C" void kernel_launch(void* const* d_in, const int* in_sizes, int n_in,
                              void* d_out, int out_size) {
    const float* preds = (const float*)d_in[0];
    const float* tgts  = (const float*)d_in[1];
    int B = in_sizes[0] / LDIM;
    if (B > BMAX) B = BMAX;
    listmle_row_kernel<<<B, NTH>>>(preds, tgts);
    listmle_mean_kernel<<<1, NTH>>>((float*)d_out, B);
}